// round 17
// baseline (speedup 1.0000x reference)
#include <cuda_runtime.h>
#include <cstdint>
#include <math.h>

// Problem constants
#define BATCH 8
#define SEQ 512
#define DM 512
#define DFF 2048
#define NH 8
#define DKH 64
#define NTOK (BATCH*SEQ)   // 4096
#define NLAYER 4
#define NFEAT 32
#define NEMB (DM-NFEAT)    // 480

// ---------------- scratch (static __device__; no allocation) ----------------
__device__ float g_enc[NTOK*DM];
__device__ float g_dec[NTOK*DM];
__device__ float g_enc_r[NTOK*DM];
__device__ float g_dec_r[NTOK*DM];
__device__ float g_qkv[3*NTOK*DM];
__device__ float g_ctx[NTOK*DM];
__device__ float g_tmp[2*NTOK*DM];
__device__ float g_ffh[NTOK*DFF];
__device__ int   g_encpad[NTOK];
__device__ int   g_decpad[NTOK];
__device__ float g_embT[NFEAT*NEMB];
// pre-rounded (tf32-RNA) weights; square mats transposed to [N][K]
#define WB_EQKV  0
#define WB_EPW   3145728
#define WB_EW1   4194304
#define WB_EW2   8388608
#define WB_DSQKV 12582912
#define WB_DSPW  15728640
#define WB_DCQKV 16777216
#define WB_DCPW  19922944
#define WB_DW1   20971520
#define WB_DW2   25165824
#define WB_TOTAL 29360128
__device__ float g_wbuf[WB_TOTAL];

// +0x1000 then HW-truncate-low-13 == cvt.rna.tf32 (ties away via carry)
__device__ __forceinline__ float rndf(float x) {
    return __uint_as_float(__float_as_uint(x) + 0x1000u);
}

__device__ __forceinline__ void mma_tf32(float c[4], const uint32_t a[4], const uint32_t b[2]) {
    asm volatile(
        "mma.sync.aligned.m16n8k8.row.col.f32.tf32.tf32.f32 "
        "{%0,%1,%2,%3}, {%4,%5,%6,%7}, {%8,%9}, {%0,%1,%2,%3};\n"
        : "+f"(c[0]), "+f"(c[1]), "+f"(c[2]), "+f"(c[3])
        : "r"(a[0]), "r"(a[1]), "r"(a[2]), "r"(a[3]), "r"(b[0]), "r"(b[1]));
}

__device__ __forceinline__ uint32_t smem_u32(const void* p) {
    uint32_t s;
    asm("{ .reg .u64 t; cvta.to.shared.u64 t, %1; cvt.u32.u64 %0, t; }"
        : "=r"(s) : "l"(p));
    return s;
}
__device__ __forceinline__ void cp16(float* smem, const float* g) {
    asm volatile("cp.async.cg.shared.global [%0], [%1], 16;\n"
                 :: "r"(smem_u32(smem)), "l"(g));
}
__device__ __forceinline__ void ldsm4(uint32_t* d, uint32_t addr) {
    asm volatile("ldmatrix.sync.aligned.m8n8.x4.shared.b16 {%0,%1,%2,%3}, [%4];"
                 : "=r"(d[0]), "=r"(d[1]), "=r"(d[2]), "=r"(d[3]) : "r"(addr));
}
#define CP_COMMIT()  asm volatile("cp.async.commit_group;\n" ::: "memory")
#define CP_WAIT0()   asm volatile("cp.async.wait_group 0;\n" ::: "memory")

// ---------------- weight prep: round FFN mats + embT (one launch) ----------
struct WSrc { const float* p[10]; };
__global__ void prep_misc(WSrc ws, float* __restrict__ wbuf,
                          const float* __restrict__ emb_w,
                          float* __restrict__ embT)
{
    int seg = blockIdx.y;
    if (seg < 4) {
        static const long offs[4] = {WB_EW1, WB_EW2, WB_DW1, WB_DW2};
        const uint4* in = (const uint4*)ws.p[seg];
        uint4* out = (uint4*)(wbuf + offs[seg]);
        int n4 = (NLAYER*DFF*DM) >> 2;
        for (int i = blockIdx.x*blockDim.x + threadIdx.x; i < n4;
             i += gridDim.x*blockDim.x) {
            uint4 v = in[i];
            v.x += 0x1000u; v.y += 0x1000u; v.z += 0x1000u; v.w += 0x1000u;
            out[i] = v;
        }
    } else {
        for (int i = blockIdx.x*blockDim.x + threadIdx.x; i < NFEAT*NEMB;
             i += gridDim.x*blockDim.x) {
            int f = i / NEMB, o = i % NEMB;
            embT[i] = emb_w[o*NFEAT + f];
        }
    }
}

// ---------------- weight prep: transpose+round 48 square 512x512 mats -------
__global__ void prep_wT(WSrc ws, float* __restrict__ wbuf)
{
    __shared__ float ts[32][33];
    int z = blockIdx.z;
    const float* src; float* dst;
    if      (z < 12) { src = ws.p[0] + (size_t)z*DM*DM;      dst = wbuf + WB_EQKV  + (size_t)z*DM*DM; }
    else if (z < 16) { src = ws.p[1] + (size_t)(z-12)*DM*DM; dst = wbuf + WB_EPW   + (size_t)(z-12)*DM*DM; }
    else if (z < 28) { src = ws.p[4] + (size_t)(z-16)*DM*DM; dst = wbuf + WB_DSQKV + (size_t)(z-16)*DM*DM; }
    else if (z < 32) { src = ws.p[5] + (size_t)(z-28)*DM*DM; dst = wbuf + WB_DSPW  + (size_t)(z-28)*DM*DM; }
    else if (z < 44) { src = ws.p[6] + (size_t)(z-32)*DM*DM; dst = wbuf + WB_DCQKV + (size_t)(z-32)*DM*DM; }
    else             { src = ws.p[7] + (size_t)(z-44)*DM*DM; dst = wbuf + WB_DCPW  + (size_t)(z-44)*DM*DM; }
    int bx = blockIdx.x*32, by = blockIdx.y*32;
    int tx = threadIdx.x, ty0 = threadIdx.y;
    #pragma unroll
    for (int j = 0; j < 4; j++) {
        int ty = ty0 + 8*j;
        ts[ty][tx] = rndf(src[(size_t)(by+ty)*DM + bx + tx]);
    }
    __syncthreads();
    #pragma unroll
    for (int j = 0; j < 4; j++) {
        int ty = ty0 + 8*j;
        dst[(size_t)(bx+ty)*DM + by + tx] = ts[tx][ty];
    }
}

// ---------------- embedding (enc+dec fused via blockIdx.y) ------------------
__global__ void embed_kernel(const float* __restrict__ inpE,
                             const float* __restrict__ inpD,
                             const float* __restrict__ embT,  // [32][480]
                             const float* __restrict__ emb_b,
                             const float* __restrict__ pos,
                             float* __restrict__ outE, float* __restrict__ outE_r,
                             float* __restrict__ outD, float* __restrict__ outD_r,
                             int* __restrict__ padE, int* __restrict__ padD)
{
    int which = blockIdx.y;
    const float* inp = which ? inpD : inpE;
    float* out   = which ? outD   : outE;
    float* out_r = which ? outD_r : outE_r;
    int*   pad   = which ? padD   : padE;

    int row = blockIdx.x;
    int s = row % SEQ;
    int d = threadIdx.x;   // 512 threads
    __shared__ float xin[NFEAT];
    if (d < NFEAT) xin[d] = inp[row*NFEAT + d];
    __syncthreads();
    float v;
    if (d < NFEAT) {
        v = xin[d];
    } else {
        int o = d - NFEAT;
        float acc = emb_b[o];
        #pragma unroll
        for (int f = 0; f < NFEAT; f++) acc += xin[f]*embT[f*NEMB + o];
        v = acc;
    }
    float o = v + pos[(s+1)*DM + d];
    out[row*DM + d] = o;
    out_r[row*DM + d] = rndf(o);
    if (d == 0) {
        float sm = 0.f;
        #pragma unroll
        for (int f = 0; f < NFEAT; f++) sm += xin[f];
        pad[row] = (sm <= -9999.0f) ? 1 : 0;
    }
}

// ---------------- TF32 tensor-core GEMM, 256x64 tiles, LDSM -----------------
// C = A[M,K] @ B[N,K]^T (+bias)(relu?)(round?).  Block 256x64x32,
// 256 threads = 8 warps (4x2), warp tile 64x32.  2 CTAs/SM (16 warps/SM).
// Each B tile serves half as many CTAs -> B L2 traffic halved.
#define NSTAGE 2
#define KT 32
#define SRS 36
#define STG_A (256*SRS)     // 9216 floats
#define STG_B (64*SRS)      // 2304 floats
#define GEMM_SMEM (NSTAGE*(STG_A+STG_B)*4)   // 92160 bytes

__global__ void __launch_bounds__(256, 2) gemm_k(
    const float* __restrict__ A, const float* __restrict__ A2,
    const float* __restrict__ B, const float* __restrict__ bias,
    float* __restrict__ C, int M, int N, int K, int doRelu, int roundC,
    int kSplit, long Bstride, long biasStride, long Cstride)
{
    extern __shared__ float dsm[];
    float* As = dsm;
    float* Bs = dsm + NSTAGE*STG_A;

    int tid = threadIdx.x;
    int z = blockIdx.z;
    const float* Au;
    int Klen;
    if (kSplit > 0) {
        int kOff = z * kSplit;
        Au = A + kOff;
        B += kOff;
        if (z) bias = nullptr;
        C += (size_t)z * Cstride;
        Klen = kSplit;
    } else {
        Au = (z == 0) ? A : A2;
        B += (size_t)z * Bstride;
        if (bias) bias += (size_t)z * biasStride;
        C += (size_t)z * Cstride;
        Klen = K;
    }

    int m0 = blockIdx.y * 256, n0 = blockIdx.x * 64;
    int warp = tid >> 5, lane = tid & 31;
    int wm = (warp & 3) * 64, wn = (warp >> 2) * 32;
    int g = lane >> 2, tg = lane & 3;

    int sub = lane >> 3, r8 = lane & 7;
    uint32_t aoff[4], boff[2];
    #pragma unroll
    for (int mf = 0; mf < 4; mf++)
        aoff[mf] = (uint32_t)(((wm + mf*16 + (sub & 1)*8 + r8)*SRS + (sub >> 1)*4) * 4);
    #pragma unroll
    for (int p = 0; p < 2; p++)
        boff[p] = (uint32_t)(((wn + (2*p + (sub >> 1))*8 + r8)*SRS + (sub & 1)*4) * 4);
    uint32_t asB = smem_u32(As), bsB = smem_u32(Bs);

    float acc[4][4][4];
    #pragma unroll
    for (int mf = 0; mf < 4; mf++)
        #pragma unroll
        for (int nf = 0; nf < 4; nf++)
            #pragma unroll
            for (int r = 0; r < 4; r++) acc[mf][nf][r] = 0.f;

    int nIter = Klen >> 5;

    auto stageLoad = [&](int st, int k0) {
        float* Ad = As + st*STG_A;
        float* Bd = Bs + st*STG_B;
        // A: 256 rows x 8 chunks = 2048; 8 per thread
        #pragma unroll
        for (int i = 0; i < 8; i++) {
            int idx = tid + 256*i;
            int row = idx >> 3, kc = (idx & 7) << 2;
            cp16(&Ad[row*SRS + kc], &Au[(size_t)(m0+row)*K + k0 + kc]);
        }
        // B: 64 rows x 8 chunks = 512; 2 per thread
        #pragma unroll
        for (int i = 0; i < 2; i++) {
            int idx = tid + 256*i;
            int row = idx >> 3, kc = (idx & 7) << 2;
            cp16(&Bd[row*SRS + kc], &B[(size_t)(n0+row)*K + k0 + kc]);
        }
    };

    auto computeKs = [&](uint32_t ab, uint32_t bb, int ks) {
        uint32_t au[4][4], bu[2][4];
        #pragma unroll
        for (int mf = 0; mf < 4; mf++)
            ldsm4(au[mf], ab + aoff[mf] + ks*32);
        #pragma unroll
        for (int p = 0; p < 2; p++)
            ldsm4(bu[p], bb + boff[p] + ks*32);
        #pragma unroll
        for (int mf = 0; mf < 4; mf++)
            #pragma unroll
            for (int nf = 0; nf < 4; nf++)
                mma_tf32(acc[mf][nf], au[mf], &bu[nf >> 1][(nf & 1)*2]);
    };

    stageLoad(0, 0);
    CP_COMMIT();

    for (int it = 0; it < nIter; it++) {
        CP_WAIT0();
        __syncthreads();
        uint32_t ab = asB + (uint32_t)((it & 1) * (STG_A*4));
        uint32_t bb = bsB + (uint32_t)((it & 1) * (STG_B*4));
        computeKs(ab, bb, 0);
        if (it + 1 < nIter) {
            stageLoad((it + 1) & 1, (it + 1)*KT);
            CP_COMMIT();
        }
        computeKs(ab, bb, 1);
        computeKs(ab, bb, 2);
        computeKs(ab, bb, 3);
    }

    #pragma unroll
    for (int mf = 0; mf < 4; mf++) {
        int row0 = m0 + wm + mf*16 + g;
        int row1 = row0 + 8;
        #pragma unroll
        for (int nf = 0; nf < 4; nf++) {
            int col = n0 + wn + nf*8 + 2*tg;
            float c0 = acc[mf][nf][0], c1 = acc[mf][nf][1];
            float c2 = acc[mf][nf][2], c3 = acc[mf][nf][3];
            if (bias) {
                float b0 = bias[col], b1 = bias[col+1];
                c0 += b0; c1 += b1; c2 += b0; c3 += b1;
            }
            if (doRelu) {
                c0 = fmaxf(c0, 0.f); c1 = fmaxf(c1, 0.f);
                c2 = fmaxf(c2, 0.f); c3 = fmaxf(c3, 0.f);
            }
            if (roundC) {
                c0 = rndf(c0); c1 = rndf(c1); c2 = rndf(c2); c3 = rndf(c3);
            }
            *(float2*)&C[(size_t)row0*N + col] = make_float2(c0, c1);
            *(float2*)&C[(size_t)row1*N + col] = make_float2(c2, c3);
        }
    }
}

// ---------------- tensor-core flash attention, 4 CTAs/SM (R14-proven) -------
#define AKS 68
#define AVS 72
#define ATT_SMEM ((64*AKS + 64*AKS + 64*AVS)*4 + 64*4)

__global__ void __launch_bounds__(128, 4) attn_tc_kernel(
    const float* __restrict__ Q, const float* __restrict__ K,
    const float* __restrict__ V, const int* __restrict__ pad,
    float* __restrict__ O, int causal)
{
    extern __shared__ float sma[];
    float* Qs = sma;
    float* Ks = Qs + 64*AKS;
    float* Vs = Ks + 64*AKS;
    int*   padf = (int*)(Vs + 64*AVS);

    int tid = threadIdx.x;
    int warp = tid >> 5, lane = tid & 31;
    int g = lane >> 2, tg = lane & 3;
    int bh = blockIdx.y, b = bh >> 3, h = bh & 7;
    int q0 = blockIdx.x * 64;
    int wq = warp * 16;
    const float scale = 0.125f;

    int sub = lane >> 3, r8 = lane & 7;
    uint32_t qa_off = (uint32_t)(((wq + (sub & 1)*8 + r8)*AKS + (sub >> 1)*4) * 4);
    uint32_t kb_off[4];
    #pragma unroll
    for (int p = 0; p < 4; p++)
        kb_off[p] = (uint32_t)(((p*16 + (sub >> 1)*8 + r8)*AKS + (sub & 1)*4) * 4);
    uint32_t qsB = smem_u32(Qs), ksB = smem_u32(Ks);

    auto stageKV = [&](int kt) {
        #pragma unroll
        for (int i = 0; i < 8; i++) {
            int idx = tid + 128*i;
            int r = idx >> 4, c4 = (idx & 15) << 2;
            size_t goff = (size_t)(b*SEQ + kt*64 + r)*DM + h*DKH + c4;
            cp16(&Ks[r*AKS + c4], &K[goff]);
            cp16(&Vs[r*AVS + c4], &V[goff]);
        }
        if (tid < 16)
            cp16((float*)&padf[tid*4],
                 (const float*)&pad[b*SEQ + kt*64 + tid*4]);
    };

    #pragma unroll
    for (int i = 0; i < 8; i++) {
        int idx = tid + 128*i;
        int r = idx >> 4, c4 = (idx & 15) << 2;
        cp16(&Qs[r*AKS + c4], &Q[(size_t)(b*SEQ + q0 + r)*DM + h*DKH + c4]);
    }
    stageKV(0);
    CP_COMMIT();

    int row0 = wq + g, row1 = wq + g + 8;
    int qg0 = q0 + row0, qg1 = q0 + row1;
    int srcA = (lane & ~3) | (tg >> 1);
    int srcB = srcA + 2;
    bool oddc = (tg & 1);

    float o[8][4];
    #pragma unroll
    for (int nf = 0; nf < 8; nf++)
        #pragma unroll
        for (int r = 0; r < 4; r++) o[nf][r] = 0.f;
    float m0 = -1e30f, m1 = -1e30f, l0 = 0.f, l1 = 0.f;

    int nkt = causal ? (q0/64 + 1) : (SEQ/64);
    for (int kt = 0; kt < nkt; kt++) {
        if (kt > 0) {
            __syncthreads();
            stageKV(kt);
            CP_COMMIT();
        }
        CP_WAIT0();
        __syncthreads();

        const uint32_t* Vu = (const uint32_t*)Vs;
        const int* pf = padf;

        float sc[8][4];
        #pragma unroll
        for (int nf = 0; nf < 8; nf++)
            #pragma unroll
            for (int r = 0; r < 4; r++) sc[nf][r] = 0.f;
        #pragma unroll
        for (int ks = 0; ks < 8; ks++) {
            uint32_t a[4], bu[4][4];
            ldsm4(a, qsB + qa_off + ks*32);
            #pragma unroll
            for (int p = 0; p < 4; p++)
                ldsm4(bu[p], ksB + kb_off[p] + ks*32);
            #pragma unroll
            for (int nf = 0; nf < 8; nf++)
                mma_tf32(sc[nf], a, &bu[nf >> 1][(nf & 1)*2]);
        }

        float tmax0 = -1e30f, tmax1 = -1e30f;
        #pragma unroll
        for (int nf = 0; nf < 8; nf++) {
            int c0 = nf*8 + 2*tg, c1 = c0 + 1;
            int kg0 = kt*64 + c0, kg1 = kt*64 + c1;
            bool p0 = (pf[c0] != 0), p1 = (pf[c1] != 0);
            sc[nf][0] = (p0 || (causal && kg0 > qg0)) ? -1e9f : sc[nf][0]*scale;
            sc[nf][1] = (p1 || (causal && kg1 > qg0)) ? -1e9f : sc[nf][1]*scale;
            sc[nf][2] = (p0 || (causal && kg0 > qg1)) ? -1e9f : sc[nf][2]*scale;
            sc[nf][3] = (p1 || (causal && kg1 > qg1)) ? -1e9f : sc[nf][3]*scale;
            tmax0 = fmaxf(tmax0, fmaxf(sc[nf][0], sc[nf][1]));
            tmax1 = fmaxf(tmax1, fmaxf(sc[nf][2], sc[nf][3]));
        }
        tmax0 = fmaxf(tmax0, __shfl_xor_sync(0xFFFFFFFFu, tmax0, 1));
        tmax0 = fmaxf(tmax0, __shfl_xor_sync(0xFFFFFFFFu, tmax0, 2));
        tmax1 = fmaxf(tmax1, __shfl_xor_sync(0xFFFFFFFFu, tmax1, 1));
        tmax1 = fmaxf(tmax1, __shfl_xor_sync(0xFFFFFFFFu, tmax1, 2));

        float mn0 = fmaxf(m0, tmax0), mn1 = fmaxf(m1, tmax1);
        float cr0 = __expf(m0 - mn0), cr1 = __expf(m1 - mn1);
        m0 = mn0; m1 = mn1;

        float pr[8][4];
        float ps0 = 0.f, ps1 = 0.f;
        #pragma unroll
        for (int nf = 0; nf < 8; nf++) {
            float p00 = __expf(sc[nf][0] - mn0);
            float p01 = __expf(sc[nf][1] - mn0);
            float p10 = __expf(sc[nf][2] - mn1);
            float p11 = __expf(sc[nf][3] - mn1);
            ps0 += p00 + p01; ps1 += p10 + p11;
            pr[nf][0] = rndf(p00);
            pr[nf][1] = rndf(p01);
            pr[nf][2] = rndf(p10);
            pr[nf][3] = rndf(p11);
        }
        ps0 += __shfl_xor_sync(0xFFFFFFFFu, ps0, 1);
        ps0 += __shfl_xor_sync(0xFFFFFFFFu, ps0, 2);
        ps1 += __shfl_xor_sync(0xFFFFFFFFu, ps1, 1);
        ps1 += __shfl_xor_sync(0xFFFFFFFFu, ps1, 2);
        l0 = l0*cr0 + ps0;
        l1 = l1*cr1 + ps1;

        #pragma unroll
        for (int nf = 0; nf < 8; nf++) {
            o[nf][0] *= cr0; o[nf][1] *= cr0;
            o[nf][2] *= cr1; o[nf][3] *= cr1;
        }

        #pragma unroll
        for (int ks = 0; ks < 8; ks++) {
            float e0 = __shfl_sync(0xFFFFFFFFu, pr[ks][0], srcA);
            float d0 = __shfl_sync(0xFFFFFFFFu, pr[ks][1], srcA);
            float e1 = __shfl_sync(0xFFFFFFFFu, pr[ks][2], srcA);
            float d1 = __shfl_sync(0xFFFFFFFFu, pr[ks][3], srcA);
            float e2 = __shfl_sync(0xFFFFFFFFu, pr[ks][0], srcB);
            float d2 = __shfl_sync(0xFFFFFFFFu, pr[ks][1], srcB);
            float e3 = __shfl_sync(0xFFFFFFFFu, pr[ks][2], srcB);
            float d3 = __shfl_sync(0xFFFFFFFFu, pr[ks][3], srcB);
            uint32_t a[4];
            a[0] = __float_as_uint(oddc ? d0 : e0);
            a[1] = __float_as_uint(oddc ? d1 : e1);
            a[2] = __float_as_uint(oddc ? d2 : e2);
            a[3] = __float_as_uint(oddc ? d3 : e3);
            #pragma unroll
            for (int nf = 0; nf < 8; nf++) {
                uint32_t bv[2];
                bv[0] = Vu[(ks*8+tg  )*AVS + nf*8 + g];
                bv[1] = Vu[(ks*8+tg+4)*AVS + nf*8 + g];
                mma_tf32(o[nf], a, bv);
            }
        }
    }

    float inv0 = 1.f / l0, inv1 = 1.f / l1;
    #pragma unroll
    for (int nf = 0; nf < 8; nf++) {
        int col = h*DKH + nf*8 + 2*tg;
        *(float2*)&O[(size_t)(b*SEQ + qg0)*DM + col] =
            make_float2(rndf(o[nf][0]*inv0), rndf(o[nf][1]*inv0));
        *(float2*)&O[(size_t)(b*SEQ + qg1)*DM + col] =
            make_float2(rndf(o[nf][2]*inv1), rndf(o[nf][3]*inv1));
    }
}

// ---------------- LayerNorm: warp-per-row, 8 rows/block ----------------------
__global__ void ln_kernel(const float* __restrict__ z1,
                          const float* __restrict__ z2,
                          const float* __restrict__ res,
                          const float* __restrict__ gb,
                          float* __restrict__ out,
                          float* __restrict__ out_r)
{
    int row = blockIdx.x*8 + (threadIdx.x >> 5);
    int lane = threadIdx.x & 31;
    size_t rb = (size_t)row*DM;
    float4 v[4];
    float s1 = 0.f, s2 = 0.f;
    #pragma unroll
    for (int k = 0; k < 4; k++) {
        int col = lane*4 + k*128;
        float4 a = *(const float4*)&z1[rb + col];
        float4 b = *(const float4*)&z2[rb + col];
        float4 r = *(const float4*)&res[rb + col];
        v[k].x = a.x + b.x + r.x;
        v[k].y = a.y + b.y + r.y;
        v[k].z = a.z + b.z + r.z;
        v[k].w = a.w + b.w + r.w;
        s1 += v[k].x + v[k].y + v[k].z + v[k].w;
        s2 += v[k].x*v[k].x + v[k].y*v[k].y + v[k].z*v[k].z + v[k].w*v[k].w;
    }
    #pragma unroll
    for (int off = 16; off; off >>= 1) {
        s1 += __shfl_xor_sync(0xFFFFFFFFu, s1, off);
        s2 += __shfl_xor_sync(0xFFFFFFFFu, s2, off);
    }
    float mean = s1 / DM;
    float var = (s2 - s1*mean) / (DM - 1);
    float inv = 1.f / (sqrtf(fmaxf(var, 0.f)) + 1e-6f);
    #pragma unroll
    for (int k = 0; k < 4; k++) {
        int col = lane*4 + k*128;
        float4 gg = *(const float4*)&gb[col];
        float4 bb = *(const float4*)&gb[DM + col];
        float4 r;
        r.x = gg.x*(v[k].x-mean)*inv + bb.x;
        r.y = gg.y*(v[k].y-mean)*inv + bb.y;
        r.z = gg.z*(v[k].z-mean)*inv + bb.z;
        r.w = gg.w*(v[k].w-mean)*inv + bb.w;
        *(float4*)&out[rb + col] = r;
        float4 rr;
        rr.x = rndf(r.x); rr.y = rndf(r.y); rr.z = rndf(r.z); rr.w = rndf(r.w);
        *(float4*)&out_r[rb + col] = rr;
    }
}

// ---------------- host orchestration ----------------------------------------
extern "C" void kernel_launch(void* const* d_in, const int* in_sizes, int n_in,
                              void* d_out, int out_size)
{
    (void)in_sizes; (void)n_in; (void)out_size;
    const float* enc_in   = (const float*)d_in[0];
    const float* dec_in   = (const float*)d_in[1];
    const float* emb_w    = (const float*)d_in[2];
    const float* emb_b    = (const float*)d_in[3];
    const float* pos      = (const float*)d_in[4];
    const float* e_qkv_w  = (const float*)d_in[5];
    const float* e_qkv_b  = (const float*)d_in[6];
    const float* e_pw     = (const float*)d_in[7];
    const float* e_pb     = (const float*)d_in[8];
    const float* e_ln1    = (const float*)d_in[9];
    const float* e_w1     = (const float*)d_in[10];
    const float* e_b1     = (const float*)d_in[11];
    const float* e_w2     = (const float*)d_in[12];
    const float* e_b2     = (const float*)d_in[13];
    const float* e_ln2    = (const float*)d_in[14];
    const float* ds_qkv_w = (const float*)d_in[15];
    const float* ds_qkv_b = (const float*)d_in[16];
    const float* ds_pw    = (const float*)d_in[17];
    const float* ds_pb    = (const float*)d_in[18];
    const float* d_ln1    = (const float*)d_in[19];
    const float* dc_qkv_w = (const float*)d_in[20];
    const float* dc_qkv_b = (const float*)d_in[21];
    const float* dc_pw    = (const float*)d_in[22];
    const float* dc_pb    = (const float*)d_in[23];
    const float* d_ln2    = (const float*)d_in[24];
    const float* d_w1     = (const float*)d_in[25];
    const float* d_b1     = (const float*)d_in[26];
    const float* d_w2     = (const float*)d_in[27];
    const float* d_b2     = (const float*)d_in[28];
    const float* d_ln3    = (const float*)d_in[29];

    float *enc, *dec, *enc_r, *dec_r, *qkv, *ctx, *tmp, *ffh, *wb, *embT;
    int *epad, *dpad;
    cudaGetSymbolAddress((void**)&enc,   g_enc);
    cudaGetSymbolAddress((void**)&dec,   g_dec);
    cudaGetSymbolAddress((void**)&enc_r, g_enc_r);
    cudaGetSymbolAddress((void**)&dec_r, g_dec_r);
    cudaGetSymbolAddress((void**)&qkv,   g_qkv);
    cudaGetSymbolAddress((void**)&ctx,   g_ctx);
    cudaGetSymbolAddress((void**)&tmp,   g_tmp);
    cudaGetSymbolAddress((void**)&ffh,   g_ffh);
    cudaGetSymbolAddress((void**)&wb,    g_wbuf);
    cudaGetSymbolAddress((void**)&embT,  g_embT);
    cudaGetSymbolAddress((void**)&epad,  g_encpad);
    cudaGetSymbolAddress((void**)&dpad,  g_decpad);
    float* qb = qkv;
    float* kb = qkv + (size_t)NTOK*DM;
    float* vb = qkv + (size_t)2*NTOK*DM;
    float* tmp2 = tmp + (size_t)NTOK*DM;

    cudaFuncSetAttribute(attn_tc_kernel,
                         cudaFuncAttributeMaxDynamicSharedMemorySize, ATT_SMEM);
    cudaFuncSetAttribute(gemm_k,
                         cudaFuncAttributeMaxDynamicSharedMemorySize, GEMM_SMEM);

    WSrc ws;
    ws.p[0] = e_qkv_w;  ws.p[1] = e_pw;   ws.p[2] = e_w1;  ws.p[3] = e_w2;
    ws.p[4] = ds_qkv_w; ws.p[5] = ds_pw;  ws.p[6] = dc_qkv_w; ws.p[7] = dc_pw;
    ws.p[8] = d_w1;     ws.p[9] = d_w2;
    WSrc wr;
    wr.p[0] = e_w1; wr.p[1] = e_w2; wr.p[2] = d_w1; wr.p[3] = d_w2;
    for (int i = 4; i < 10; i++) wr.p[i] = e_w1;
    prep_misc<<<dim3(256, 5), 256>>>(wr, wb, emb_w, embT);
    prep_wT<<<dim3(16, 16, 48), dim3(32, 8)>>>(ws, wb);

    auto MHA = [&](float* x_q, float* xq_r, float* xkv_r,
                   const float* qkvw, const float* qkvb,
                   const float* pw, const float* pb, const float* lnp,
                   const int* padv, int causal, float* x_out, float* xout_r) {
        gemm_k<<<dim3(DM/64, NTOK/256, 3), 256, GEMM_SMEM>>>(
            xq_r, xkv_r, qkvw, qkvb, qb, NTOK, DM, DM, 0, 1,
            0, (long)DM*DM, (long)DM, (long)NTOK*DM);
        attn_tc_kernel<<<dim3(SEQ/64, BATCH*NH), 128, ATT_SMEM>>>(
            qb, kb, vb, padv, ctx, causal);
        gemm_k<<<dim3(DM/64, NTOK/256, 2), 256, GEMM_SMEM>>>(
            ctx, ctx, pw, pb, tmp, NTOK, DM, DM, 0, 0,
            DM/2, 0, 0, (long)NTOK*DM);
        ln_kernel<<<NTOK/8, 256>>>(tmp, tmp2, x_q, lnp, x_out, xout_r);
    };
    auto FFN = [&](float* x, float* x_r, const float* w1, const float* b1,
                   const float* w2, const float* b2, const float* lnp,
                   float* x_out, float* xout_r) {
        gemm_k<<<dim3(DFF/64, NTOK/256, 1), 256, GEMM_SMEM>>>(
            x_r, x_r, w1, b1, ffh, NTOK, DFF, DM, 1, 1,
            0, 0, 0, 0);
        gemm_k<<<dim3(DM/64, NTOK/256, 2), 256, GEMM_SMEM>>>(
            ffh, ffh, w2, b2, tmp, NTOK, DM, DFF, 0, 0,
            DFF/2, 0, 0, (long)NTOK*DM);
        ln_kernel<<<NTOK/8, 256>>>(tmp, tmp2, x, lnp, x_out, xout_r);
    };

    embed_kernel<<<dim3(NTOK, 2), 512>>>(enc_in, dec_in, embT, emb_b, pos,
                                         enc, enc_r, dec, dec_r, epad, dpad);

    for (int l = 0; l < NLAYER; l++) {
        MHA(enc, enc_r, enc_r, wb + WB_EQKV + (size_t)l*3*DM*DM, e_qkv_b + l*3*DM,
            wb + WB_EPW + (size_t)l*DM*DM, e_pb + l*DM, e_ln1 + l*2*DM,
            epad, 0, enc, enc_r);
        FFN(enc, enc_r, wb + WB_EW1 + (size_t)l*DFF*DM, e_b1 + l*DFF,
            wb + WB_EW2 + (size_t)l*DM*DFF, e_b2 + l*DM, e_ln2 + l*2*DM,
            enc, enc_r);
    }
    for (int l = 0; l < NLAYER; l++) {
        MHA(dec, dec_r, dec_r, wb + WB_DSQKV + (size_t)l*3*DM*DM, ds_qkv_b + l*3*DM,
            wb + WB_DSPW + (size_t)l*DM*DM, ds_pb + l*DM, d_ln1 + l*2*DM,
            dpad, 1, dec, dec_r);
        MHA(dec, dec_r, enc_r, wb + WB_DCQKV + (size_t)l*3*DM*DM, dc_qkv_b + l*3*DM,
            wb + WB_DCPW + (size_t)l*DM*DM, dc_pb + l*DM, d_ln2 + l*2*DM,
            epad, 0, dec, dec_r);
        float* outp = (l == NLAYER-1) ? (float*)d_out : dec;
        FFN(dec, dec_r, wb + WB_DW1 + (size_t)l*DFF*DM, d_b1 + l*DFF,
            wb + WB_DW2 + (size_t)l*DM*DFF, d_b2 + l*DM, d_ln3 + l*2*DM,
            outp, dec_r);
    }
}